// round 15
// baseline (speedup 1.0000x reference)
#include <cuda_runtime.h>
#include <cstddef>

// Problem dims (fixed)
#define T_STEPS 128
#define BATCH   2048
#define IN0     18
#define H       256
#define G3      768   // 3*H
#define NBR     14    // real batch rows per block tile (= rows per thread)
#define NBP     16    // padded row stride in smem/xT (keeps 16B alignment)
#define NBLKK   147   // 146 full tiles + 1 overlapping tail tile -> one wave on 148 SMs
#define NTHR    256   // one thread per hidden unit j

typedef unsigned long long u64;

// ---------------- scratch ----------------
// SoA transposed weights: [k][gate*H + j] -> per (k, gate) a warp's 32 loads are
// one contiguous 128B line; no pad waste (L2 traffic -25% vs float4 packing).
__device__ float g_Wt_hh0[H * G3];
__device__ float g_Wt_hh1[H * G3];
__device__ float g_Wt_ih1[H * G3];
__device__ float g_xT[(size_t)T_STEPS * NBLKK * IN0 * NBP];  // [t][blk][i][row16]
__device__ float g_h2[BATCH * H];    // layer-1 final hidden, [b][c]

__device__ __forceinline__ int blk_start(int blk) {
    return (blk < NBLKK - 1) ? NBR * blk : (BATCH - NBR);
}

// ---------------- packed fp32x2 helpers ----------------
__device__ __forceinline__ u64 pk2(float a, float b) {
    u64 r; asm("mov.b64 %0, {%1, %2};" : "=l"(r) : "f"(a), "f"(b)); return r;
}
__device__ __forceinline__ void fma2(u64& d, u64 a, u64 b) {
    asm("fma.rn.f32x2 %0, %1, %2, %0;" : "+l"(d) : "l"(a), "l"(b));
}
__device__ __forceinline__ float2 up2(u64 p) {
    float2 f; asm("mov.b64 {%0, %1}, %2;" : "=f"(f.x), "=f"(f.y) : "l"(p)); return f;
}
__device__ __forceinline__ float sigf(float x) {
    return __fdividef(1.f, 1.f + __expf(-x));
}
__device__ __forceinline__ float tanhf_fast(float x) {
    return 2.f * sigf(2.f * x) - 1.f;
}

// ---------------- transpose [3H x H] -> SoA [k][gate*H + j] ----------------
__global__ void k_transpose(const float* __restrict__ src, int which) {
    float* dst = (which == 0) ? g_Wt_hh0 : (which == 1) ? g_Wt_hh1 : g_Wt_ih1;
    int idx = blockIdx.x * 256 + threadIdx.x;   // grid = 768 blocks
    int k = idx / G3;
    int g = idx - k * G3;        // g = gate*H + j
    dst[idx] = src[g * H + k];
}

// ---------------- pre-transpose x: [t][b][i] -> [t][blk][i][row16] ----------------
__global__ void k_xt(const float* __restrict__ x) {
    size_t idx = (size_t)blockIdx.x * 256 + threadIdx.x;
    const size_t total = (size_t)T_STEPS * NBLKK * IN0 * NBR;
    if (idx >= total) return;
    int row = (int)(idx % NBR);
    size_t r1 = idx / NBR;
    int i = (int)(r1 % IN0);
    size_t r2 = r1 / IN0;
    int blk = (int)(r2 % NBLKK);
    int t = (int)(r2 / NBLKK);
    int b = blk_start(blk) + row;
    g_xT[(((size_t)t * NBLKK + blk) * IN0 + i) * NBP + row] =
        x[((size_t)t * BATCH + b) * IN0 + i];
}

// load one 14-wide padded row (7 u64) from ptr (16B-aligned, stride NBP floats)
#define LOAD_ROW(ptr, b0, b1, b2, b3v)                                       \
    ulonglong2 b0, b1, b2; u64 b3v;                                          \
    do {                                                                     \
        const ulonglong2* _hp = (const ulonglong2*)(ptr);                    \
        b0 = _hp[0]; b1 = _hp[1]; b2 = _hp[2];                               \
        b3v = ((const u64*)(ptr))[6];                                        \
    } while (0)

// fma a 14-batch row (7 u64) against one gate weight into 7 accumulators
#define ROW_FMA(acc, wv, b0, b1, b2, b3v)                                    \
    do {                                                                     \
        fma2(acc[0], b0.x, wv); fma2(acc[1], b0.y, wv);                      \
        fma2(acc[2], b1.x, wv); fma2(acc[3], b1.y, wv);                      \
        fma2(acc[4], b2.x, wv); fma2(acc[5], b2.y, wv);                      \
        fma2(acc[6], b3v, wv);                                               \
    } while (0)

// ---- fused triple-matrix gemm: L1(t) [Wih1*h0 + Whh1*h1] and L0(t+1) [Whh0*h0] ----
// h0 row loaded once for Wih1 + Whh0 sides. SoA weights: 9 scalar LDG per k.
// chunk=2 double buffer.
__device__ __forceinline__ void gemm_tri(const float* __restrict__ sh0row,
                                         const float* __restrict__ sh1row,
                                         u64* __restrict__ a1r, u64* __restrict__ a1z,
                                         u64* __restrict__ a1xn, u64* __restrict__ a1hn,
                                         u64* __restrict__ a0r, u64* __restrict__ a0z,
                                         u64* __restrict__ a0hn, int j) {
    const float* pi1 = g_Wt_ih1 + j;
    const float* ph1 = g_Wt_hh1 + j;
    const float* ph0 = g_Wt_hh0 + j;
    float wb[2][2][9];   // [buf][kk][(mat,gate)]
#pragma unroll
    for (int kk = 0; kk < 2; kk++) {
        const int o = kk * G3;
        wb[0][kk][0] = __ldg(pi1 + o);
        wb[0][kk][1] = __ldg(pi1 + o + H);
        wb[0][kk][2] = __ldg(pi1 + o + 2 * H);
        wb[0][kk][3] = __ldg(ph1 + o);
        wb[0][kk][4] = __ldg(ph1 + o + H);
        wb[0][kk][5] = __ldg(ph1 + o + 2 * H);
        wb[0][kk][6] = __ldg(ph0 + o);
        wb[0][kk][7] = __ldg(ph0 + o + H);
        wb[0][kk][8] = __ldg(ph0 + o + 2 * H);
    }
#pragma unroll 2
    for (int c = 0; c < H / 2; c++) {
        const int cur = c & 1, nxt = cur ^ 1;
        if (c + 1 < H / 2) {
#pragma unroll
            for (int kk = 0; kk < 2; kk++) {
                const int o = ((c + 1) * 2 + kk) * G3;
                wb[nxt][kk][0] = __ldg(pi1 + o);
                wb[nxt][kk][1] = __ldg(pi1 + o + H);
                wb[nxt][kk][2] = __ldg(pi1 + o + 2 * H);
                wb[nxt][kk][3] = __ldg(ph1 + o);
                wb[nxt][kk][4] = __ldg(ph1 + o + H);
                wb[nxt][kk][5] = __ldg(ph1 + o + 2 * H);
                wb[nxt][kk][6] = __ldg(ph0 + o);
                wb[nxt][kk][7] = __ldg(ph0 + o + H);
                wb[nxt][kk][8] = __ldg(ph0 + o + 2 * H);
            }
        }
#pragma unroll
        for (int kk = 0; kk < 2; kk++) {
            const int k = c * 2 + kk;
            const float* w = wb[cur][kk];
            // h0 row: feeds L1 input-side AND L0 hidden-side
            {
                LOAD_ROW(sh0row + k * NBP, b0, b1, b2, b3v);
                u64 w1 = pk2(w[0], w[0]), w2 = pk2(w[1], w[1]), w3 = pk2(w[2], w[2]);
                ROW_FMA(a1r, w1, b0, b1, b2, b3v);
                ROW_FMA(a1z, w2, b0, b1, b2, b3v);
                ROW_FMA(a1xn, w3, b0, b1, b2, b3v);
                u64 w4 = pk2(w[6], w[6]), w5 = pk2(w[7], w[7]), w6 = pk2(w[8], w[8]);
                ROW_FMA(a0r, w4, b0, b1, b2, b3v);
                ROW_FMA(a0z, w5, b0, b1, b2, b3v);
                ROW_FMA(a0hn, w6, b0, b1, b2, b3v);
            }
            // h1 row: L1 hidden-side
            {
                LOAD_ROW(sh1row + k * NBP, b0, b1, b2, b3v);
                u64 w1 = pk2(w[3], w[3]), w2 = pk2(w[4], w[4]), w3 = pk2(w[5], w[5]);
                ROW_FMA(a1r, w1, b0, b1, b2, b3v);
                ROW_FMA(a1z, w2, b0, b1, b2, b3v);
                ROW_FMA(a1hn, w3, b0, b1, b2, b3v);
            }
        }
    }
}

// gates -> hnew[14]; old h read from smem slice (thread-private)
__device__ __forceinline__ void epilogue(u64* ar, u64* az, u64* axn, u64* ahn,
                                         const float* hold, float* hnew) {
#pragma unroll
    for (int p = 0; p < 7; p++) {
        float2 r2 = up2(ar[p]), z2 = up2(az[p]), x2 = up2(axn[p]), h2 = up2(ahn[p]);
        float r0 = sigf(r2.x), z0 = sigf(z2.x);
        float n0 = tanhf_fast(x2.x + r0 * h2.x);
        hnew[2 * p] = n0 + z0 * (hold[2 * p] - n0);
        float r1 = sigf(r2.y), z1 = sigf(z2.y);
        float n1 = tanhf_fast(x2.y + r1 * h2.y);
        hnew[2 * p + 1] = n1 + z1 * (hold[2 * p + 1] - n1);
    }
}

// write hnew[14] to a padded row (3x float4 + 1x float2)
__device__ __forceinline__ void store_row(float* dst, const float* hnew) {
    float4* w4 = (float4*)dst;
    w4[0] = make_float4(hnew[0], hnew[1], hnew[2], hnew[3]);
    w4[1] = make_float4(hnew[4], hnew[5], hnew[6], hnew[7]);
    w4[2] = make_float4(hnew[8], hnew[9], hnew[10], hnew[11]);
    ((float2*)(dst + 12))[0] = make_float2(hnew[12], hnew[13]);
}

// ---------------- fused 2-layer GRU, layer-pipelined: ONE phase + ONE barrier per step ----------------
// Phase p computes L1(p) [h1(p) from h0(p), h1(p-1)] AND L0(p+1) [h0(p+1) from h0(p), x(p+1)].
__global__ __launch_bounds__(NTHR, 1)
void k_gru(const float* __restrict__ Wih0,
           const float* __restrict__ bih0, const float* __restrict__ bhh0,
           const float* __restrict__ bih1, const float* __restrict__ bhh1) {
    extern __shared__ float smem[];
    float* sWih = smem;                       // [i][g], 18*768 = 13824
    float* sh0  = sWih + IN0 * G3;            // layer-0 h, 2 bufs x [c][row16]
    float* sh1  = sh0 + 2 * H * NBP;          // layer-1 h, 2 bufs
    float* sx   = sh1 + 2 * H * NBP;          // x tile, 2 bufs x [i][row16]

    const int j = threadIdx.x;
    const int bbase = blk_start(blockIdx.x);
    const size_t xtile = (size_t)IN0 * NBP;

    for (int idx = j; idx < IN0 * G3; idx += NTHR) {
        int i = idx / G3, g = idx - i * G3;
        sWih[idx] = Wih0[g * IN0 + i];
    }
    // zero buffer 0 of both states (phase 0 reads buf 0)
    for (int idx = j; idx < H * NBP; idx += NTHR) {
        sh0[idx] = 0.f;
        sh1[idx] = 0.f;
    }
    // stage x(0) into sx[1] (prologue input) and x(1) into sx[0] (phase-0 input)
    {
        const float4* s0 = (const float4*)(g_xT + ((size_t)0 * NBLKK + blockIdx.x) * xtile);
        const float4* s1 = (const float4*)(g_xT + ((size_t)1 * NBLKK + blockIdx.x) * xtile);
        float4* d1 = (float4*)(sx + IN0 * NBP);
        float4* d0 = (float4*)sx;
        for (int idx = j; idx < IN0 * NBP / 4; idx += NTHR) {
            d1[idx] = s0[idx];
            d0[idx] = s1[idx];
        }
    }

    const float brz0 = bih0[j] + bhh0[j];
    const float bzz0 = bih0[H + j] + bhh0[H + j];
    const float bxn0 = bih0[2 * H + j];
    const float bhn0 = bhh0[2 * H + j];
    const float brz1 = bih1[j] + bhh1[j];
    const float bzz1 = bih1[H + j] + bhh1[H + j];
    const float bxn1 = bih1[2 * H + j];
    const float bhn1 = bhh1[2 * H + j];
    __syncthreads();

    // input projection K=18 from sxbuf into (ar, az, axn)
#define INPUT_PROJ(sxbuf, ar, az, axn)                                        \
    do {                                                                      \
        _Pragma("unroll")                                                     \
        for (int i = 0; i < IN0; i++) {                                       \
            float wr = sWih[i * G3 + j];                                      \
            float wz = sWih[i * G3 + H + j];                                  \
            float wn = sWih[i * G3 + 2 * H + j];                              \
            u64 wr2 = pk2(wr, wr), wz2 = pk2(wz, wz), wn2 = pk2(wn, wn);      \
            LOAD_ROW((sxbuf) + i * NBP, b0, b1, b2, b3v);                     \
            ROW_FMA(ar, wr2, b0, b1, b2, b3v);                                \
            ROW_FMA(az, wz2, b0, b1, b2, b3v);                                \
            ROW_FMA(axn, wn2, b0, b1, b2, b3v);                               \
        }                                                                     \
    } while (0)

    // ---------- prologue: h0(0) from x(0) (hidden state is zero) ----------
    {
        u64 a0r[7], a0z[7], a0xn[7], a0hn[7];
#pragma unroll
        for (int p = 0; p < 7; p++) {
            a0r[p] = pk2(brz0, brz0); a0z[p] = pk2(bzz0, bzz0);
            a0xn[p] = pk2(bxn0, bxn0); a0hn[p] = pk2(bhn0, bhn0);
        }
        INPUT_PROJ(sx + IN0 * NBP, a0r, a0z, a0xn);
        float hnew[NBR];
        float hzero[NBR];
#pragma unroll
        for (int b = 0; b < NBR; b++) hzero[b] = 0.f;
        epilogue(a0r, a0z, a0xn, a0hn, hzero, hnew);
        store_row(sh0 + j * NBP, hnew);   // h0(0) -> buf 0
    }
    __syncthreads();

    // ---------- main: 128 phases, one barrier each ----------
    for (int p = 0; p < T_STEPS; p++) {
        const int tc = p & 1, tn = tc ^ 1;
        const float* sh0c = sh0 + tc * (H * NBP);   // h0(p)
        float*       sh0n = sh0 + tn * (H * NBP);
        const float* sh1c = sh1 + tc * (H * NBP);   // h1(p-1)
        float*       sh1n = sh1 + tn * (H * NBP);
        const float* sxc  = sx + tc * (IN0 * NBP);  // x(p+1)

        u64 a1r[7], a1z[7], a1xn[7], a1hn[7];
        u64 a0r[7], a0z[7], a0xn[7], a0hn[7];
#pragma unroll
        for (int q = 0; q < 7; q++) {
            a1r[q] = pk2(brz1, brz1); a1z[q] = pk2(bzz1, bzz1);
            a1xn[q] = pk2(bxn1, bxn1); a1hn[q] = pk2(bhn1, bhn1);
            a0r[q] = pk2(brz0, brz0); a0z[q] = pk2(bzz0, bzz0);
            a0xn[q] = pk2(bxn0, bxn0); a0hn[q] = pk2(bhn0, bhn0);
        }

        INPUT_PROJ(sxc, a0r, a0z, a0xn);                      // L0(p+1) input part
        gemm_tri(sh0c, sh1c, a1r, a1z, a1xn, a1hn, a0r, a0z, a0hn, j);

        // stage x(p+2) into the other sx buffer
        if (p + 2 < T_STEPS) {
            const float4* src =
                (const float4*)(g_xT + ((size_t)(p + 2) * NBLKK + blockIdx.x) * xtile);
            float4* dst = (float4*)(sx + tn * (IN0 * NBP));
            for (int idx = j; idx < IN0 * NBP / 4; idx += NTHR) dst[idx] = src[idx];
        }

        // epilogue L1(p): h1(p) from h1(p-1)
        {
            float hnew[NBR];
            epilogue(a1r, a1z, a1xn, a1hn, sh1c + j * NBP, hnew);
            store_row(sh1n + j * NBP, hnew);
            if (p == T_STEPS - 1) {
#pragma unroll
                for (int b = 0; b < NBR; b++)
                    g_h2[(size_t)(bbase + b) * H + j] = hnew[b];
            }
        }
        // epilogue L0(p+1): h0(p+1) from h0(p)  (p=127: dead value, never read)
        {
            float hnew[NBR];
            epilogue(a0r, a0z, a0xn, a0hn, sh0c + j * NBP, hnew);
            store_row(sh0n + j * NBP, hnew);
        }
        __syncthreads();   // phase results visible
    }
#undef INPUT_PROJ
}

// ---------------- FC head ----------------
__global__ void k_fc(const float* __restrict__ fcw, const float* __restrict__ fcb,
                     float* __restrict__ out) {
    int warp = threadIdx.x >> 5, lane = threadIdx.x & 31;
    int row = blockIdx.x * 8 + warp;
    const float* h = &g_h2[(size_t)row * H];
    float a0 = 0.f, a1 = 0.f, a2 = 0.f, a3 = 0.f;
    for (int k = lane; k < H; k += 32) {
        float hv = h[k];
        a0 += hv * fcw[k];
        a1 += hv * fcw[H + k];
        a2 += hv * fcw[2 * H + k];
        a3 += hv * fcw[3 * H + k];
    }
#pragma unroll
    for (int off = 16; off; off >>= 1) {
        a0 += __shfl_xor_sync(0xffffffffu, a0, off);
        a1 += __shfl_xor_sync(0xffffffffu, a1, off);
        a2 += __shfl_xor_sync(0xffffffffu, a2, off);
        a3 += __shfl_xor_sync(0xffffffffu, a3, off);
    }
    if (lane == 0) {
        float l0 = a0 + fcb[0], l1 = a1 + fcb[1], l2 = a2 + fcb[2], l3 = a3 + fcb[3];
        out[row * 4 + 0] = 2.f / (1.f + expf(-l0)) - 1.f;
        out[row * 4 + 1] = 2.f / (1.f + expf(-l1)) - 1.f;
        out[row * 4 + 2] = 2.f / (1.f + expf(-l2)) - 1.f;
        out[row * 4 + 3] = 2.f / (1.f + expf(-l3)) - 1.f;
    }
}

extern "C" void kernel_launch(void* const* d_in, const int* in_sizes, int n_in,
                              void* d_out, int out_size) {
    const float* x    = (const float*)d_in[0];
    const float* Wih0 = (const float*)d_in[1];
    const float* Whh0 = (const float*)d_in[2];
    const float* bih0 = (const float*)d_in[3];
    const float* bhh0 = (const float*)d_in[4];
    const float* Wih1 = (const float*)d_in[5];
    const float* Whh1 = (const float*)d_in[6];
    const float* bih1 = (const float*)d_in[7];
    const float* bhh1 = (const float*)d_in[8];
    const float* fcw  = (const float*)d_in[9];
    const float* fcb  = (const float*)d_in[10];
    float* out = (float*)d_out;

    // floats: sWih 13824 + sh0 8192 + sh1 8192 + sx 576 = 30784 -> 123136 B
    const int gru_smem = (IN0 * G3 + 4 * H * NBP + 2 * IN0 * NBP) * (int)sizeof(float);
    static int smem_set = 0;
    if (!smem_set) {
        cudaFuncSetAttribute(k_gru, cudaFuncAttributeMaxDynamicSharedMemorySize, gru_smem);
        smem_set = 1;
    }

    {
        const size_t total = (size_t)T_STEPS * NBLKK * IN0 * NBR;
        k_xt<<<(int)((total + 255) / 256), 256>>>(x);
    }
    k_transpose<<<G3, 256>>>(Whh0, 0);
    k_transpose<<<G3, 256>>>(Whh1, 1);
    k_transpose<<<G3, 256>>>(Wih1, 2);
    k_gru<<<NBLKK, NTHR, gru_smem>>>(Wih0, bih0, bhh0, bih1, bhh1);
    k_fc<<<BATCH / 8, 256>>>(fcw, fcb, out);
}

// round 17
// speedup vs baseline: 1.0323x; 1.0323x over previous
#include <cuda_runtime.h>
#include <cstddef>

// Problem dims (fixed)
#define T_STEPS 128
#define BATCH   2048
#define IN0     18
#define H       256
#define G3      768   // 3*H
#define NBR     14    // real batch rows per block tile (= rows per thread)
#define NBP     16    // padded row stride in smem/xT (keeps 16B alignment)
#define NBLKK   147   // 146 full tiles + 1 overlapping tail tile -> one wave on 148 SMs
#define NTHR    256   // one thread per hidden unit j

typedef unsigned long long u64;

// ---------------- scratch ----------------
// Dense 4-k gate packing: for k-group kg (4 k's) and unit j, the 12 gate weights
// (k0:r,z,n, k1:r,z,n, k2:r,z,n, k3:r,z,n) are stored as 3 dense float4 planes:
//   addr(kg, w, j) = (kg*3 + w)*256 + j,  w in 0..2
// A=(r0,z0,n0,r1)  B=(z1,n1,r2,z2)  C=(n2,r3,z3,n3).  No pad: 48B per 4k per j.
#define WGROUPS (H / 4)           // 64 k-groups
__device__ float4 g_Wp_hh0[WGROUPS * 3 * 256];
__device__ float4 g_Wp_hh1[WGROUPS * 3 * 256];
__device__ float4 g_Wp_ih1[WGROUPS * 3 * 256];
__device__ float g_xT[(size_t)T_STEPS * NBLKK * IN0 * NBP];  // [t][blk][i][row16]
__device__ float g_h2[BATCH * H];    // layer-1 final hidden, [b][c]

__device__ __forceinline__ int blk_start(int blk) {
    return (blk < NBLKK - 1) ? NBR * blk : (BATCH - NBR);
}

// ---------------- packed fp32x2 helpers ----------------
__device__ __forceinline__ u64 pk2(float a, float b) {
    u64 r; asm("mov.b64 %0, {%1, %2};" : "=l"(r) : "f"(a), "f"(b)); return r;
}
__device__ __forceinline__ void fma2(u64& d, u64 a, u64 b) {
    asm("fma.rn.f32x2 %0, %1, %2, %0;" : "+l"(d) : "l"(a), "l"(b));
}
__device__ __forceinline__ float2 up2(u64 p) {
    float2 f; asm("mov.b64 {%0, %1}, %2;" : "=f"(f.x), "=f"(f.y) : "l"(p)); return f;
}
__device__ __forceinline__ float sigf(float x) {
    return __fdividef(1.f, 1.f + __expf(-x));
}
__device__ __forceinline__ float tanhf_fast(float x) {
    return 2.f * sigf(2.f * x) - 1.f;
}

// ---------------- transpose [3H x H] -> dense 4-k gate packing ----------------
__global__ void k_transpose(const float* __restrict__ src, int which) {
    float* dst = (which == 0) ? (float*)g_Wp_hh0
               : (which == 1) ? (float*)g_Wp_hh1 : (float*)g_Wp_ih1;
    int dstf = blockIdx.x * 256 + threadIdx.x;   // grid = 768 blocks -> 196608 floats
    int c  = dstf & 3;
    int j  = (dstf >> 2) & 255;
    int wg = dstf >> 10;          // (kg*3 + w)
    int w  = wg % 3;
    int kg = wg / 3;
    int idx12 = w * 4 + c;        // position within the 12 packed gate values
    int koff = idx12 / 3, gate = idx12 - koff * 3;
    int k = kg * 4 + koff;
    dst[dstf] = src[(gate * H + j) * H + k];
}

// ---------------- pre-transpose x: [t][b][i] -> [t][blk][i][row16] ----------------
__global__ void k_xt(const float* __restrict__ x) {
    size_t idx = (size_t)blockIdx.x * 256 + threadIdx.x;
    const size_t total = (size_t)T_STEPS * NBLKK * IN0 * NBR;
    if (idx >= total) return;
    int row = (int)(idx % NBR);
    size_t r1 = idx / NBR;
    int i = (int)(r1 % IN0);
    size_t r2 = r1 / IN0;
    int blk = (int)(r2 % NBLKK);
    int t = (int)(r2 / NBLKK);
    int b = blk_start(blk) + row;
    g_xT[(((size_t)t * NBLKK + blk) * IN0 + i) * NBP + row] =
        x[((size_t)t * BATCH + b) * IN0 + i];
}

// load one 14-wide padded row (7 u64) from ptr (16B-aligned, stride NBP floats)
#define LOAD_ROW(ptr, b0, b1, b2, b3v)                                       \
    ulonglong2 b0, b1, b2; u64 b3v;                                          \
    do {                                                                     \
        const ulonglong2* _hp = (const ulonglong2*)(ptr);                    \
        b0 = _hp[0]; b1 = _hp[1]; b2 = _hp[2];                               \
        b3v = ((const u64*)(ptr))[6];                                        \
    } while (0)

// fma a 14-batch row (7 u64) against one gate weight into 7 accumulators
#define ROW_FMA(acc, wv, b0, b1, b2, b3v)                                    \
    do {                                                                     \
        fma2(acc[0], b0.x, wv); fma2(acc[1], b0.y, wv);                      \
        fma2(acc[2], b1.x, wv); fma2(acc[3], b1.y, wv);                      \
        fma2(acc[4], b2.x, wv); fma2(acc[5], b2.y, wv);                      \
        fma2(acc[6], b3v, wv);                                               \
    } while (0)

// ---- fused triple-matrix gemm: L1(t) [Wih1*h0 + Whh1*h1] and L0(t+1) [Whh0*h0] ----
// Dense packed weights: 9 LDG.128 per 4-k group (3 per matrix). h0 row loaded once
// for Wih1 + Whh0 sides. Double-buffered group prefetch.
__device__ __forceinline__ void gemm_tri(const float* __restrict__ sh0row,
                                         const float* __restrict__ sh1row,
                                         u64* __restrict__ a1r, u64* __restrict__ a1z,
                                         u64* __restrict__ a1xn, u64* __restrict__ a1hn,
                                         u64* __restrict__ a0r, u64* __restrict__ a0z,
                                         u64* __restrict__ a0hn, int j) {
    const float4* pi1 = g_Wp_ih1 + j;
    const float4* ph1 = g_Wp_hh1 + j;
    const float4* ph0 = g_Wp_hh0 + j;
    float4 wb[2][9];   // [buf][mat*3 + w]
#pragma unroll
    for (int w = 0; w < 3; w++) {
        wb[0][0 + w] = __ldg(pi1 + w * 256);
        wb[0][3 + w] = __ldg(ph1 + w * 256);
        wb[0][6 + w] = __ldg(ph0 + w * 256);
    }
#pragma unroll 2
    for (int g = 0; g < WGROUPS; g++) {
        const int cur = g & 1, nxt = cur ^ 1;
        if (g + 1 < WGROUPS) {
#pragma unroll
            for (int w = 0; w < 3; w++) {
                wb[nxt][0 + w] = __ldg(pi1 + ((g + 1) * 3 + w) * 256);
                wb[nxt][3 + w] = __ldg(ph1 + ((g + 1) * 3 + w) * 256);
                wb[nxt][6 + w] = __ldg(ph0 + ((g + 1) * 3 + w) * 256);
            }
        }
        // view the 9 float4s as 3 matrices x 12 gate floats (compile-time indexing)
        const float* W = (const float*)&wb[cur][0];
        // W[0..11]  = Wih1 gates (k0:r,z,n ... k3:r,z,n)
        // W[12..23] = Whh1 gates
        // W[24..35] = Whh0 gates
#pragma unroll
        for (int kk = 0; kk < 4; kk++) {
            const int k = g * 4 + kk;
            // h0 row: feeds L1 input-side AND L0 hidden-side
            {
                LOAD_ROW(sh0row + k * NBP, b0, b1, b2, b3v);
                u64 w1 = pk2(W[kk * 3 + 0], W[kk * 3 + 0]);
                u64 w2 = pk2(W[kk * 3 + 1], W[kk * 3 + 1]);
                u64 w3 = pk2(W[kk * 3 + 2], W[kk * 3 + 2]);
                ROW_FMA(a1r, w1, b0, b1, b2, b3v);
                ROW_FMA(a1z, w2, b0, b1, b2, b3v);
                ROW_FMA(a1xn, w3, b0, b1, b2, b3v);
                u64 w4 = pk2(W[24 + kk * 3 + 0], W[24 + kk * 3 + 0]);
                u64 w5 = pk2(W[24 + kk * 3 + 1], W[24 + kk * 3 + 1]);
                u64 w6 = pk2(W[24 + kk * 3 + 2], W[24 + kk * 3 + 2]);
                ROW_FMA(a0r, w4, b0, b1, b2, b3v);
                ROW_FMA(a0z, w5, b0, b1, b2, b3v);
                ROW_FMA(a0hn, w6, b0, b1, b2, b3v);
            }
            // h1 row: L1 hidden-side
            {
                LOAD_ROW(sh1row + k * NBP, b0, b1, b2, b3v);
                u64 w1 = pk2(W[12 + kk * 3 + 0], W[12 + kk * 3 + 0]);
                u64 w2 = pk2(W[12 + kk * 3 + 1], W[12 + kk * 3 + 1]);
                u64 w3 = pk2(W[12 + kk * 3 + 2], W[12 + kk * 3 + 2]);
                ROW_FMA(a1r, w1, b0, b1, b2, b3v);
                ROW_FMA(a1z, w2, b0, b1, b2, b3v);
                ROW_FMA(a1hn, w3, b0, b1, b2, b3v);
            }
        }
    }
}

// gates -> hnew[14]; old h read from smem slice (thread-private)
__device__ __forceinline__ void epilogue(u64* ar, u64* az, u64* axn, u64* ahn,
                                         const float* hold, float* hnew) {
#pragma unroll
    for (int p = 0; p < 7; p++) {
        float2 r2 = up2(ar[p]), z2 = up2(az[p]), x2 = up2(axn[p]), h2 = up2(ahn[p]);
        float r0 = sigf(r2.x), z0 = sigf(z2.x);
        float n0 = tanhf_fast(x2.x + r0 * h2.x);
        hnew[2 * p] = n0 + z0 * (hold[2 * p] - n0);
        float r1 = sigf(r2.y), z1 = sigf(z2.y);
        float n1 = tanhf_fast(x2.y + r1 * h2.y);
        hnew[2 * p + 1] = n1 + z1 * (hold[2 * p + 1] - n1);
    }
}

// write hnew[14] to a padded row (3x float4 + 1x float2)
__device__ __forceinline__ void store_row(float* dst, const float* hnew) {
    float4* w4 = (float4*)dst;
    w4[0] = make_float4(hnew[0], hnew[1], hnew[2], hnew[3]);
    w4[1] = make_float4(hnew[4], hnew[5], hnew[6], hnew[7]);
    w4[2] = make_float4(hnew[8], hnew[9], hnew[10], hnew[11]);
    ((float2*)(dst + 12))[0] = make_float2(hnew[12], hnew[13]);
}

// ---------------- fused 2-layer GRU, layer-pipelined: ONE phase + ONE barrier per step ----------------
// Phase p computes L1(p) [h1(p) from h0(p), h1(p-1)] AND L0(p+1) [h0(p+1) from h0(p), x(p+1)].
__global__ __launch_bounds__(NTHR, 1)
void k_gru(const float* __restrict__ Wih0,
           const float* __restrict__ bih0, const float* __restrict__ bhh0,
           const float* __restrict__ bih1, const float* __restrict__ bhh1) {
    extern __shared__ float smem[];
    float* sWih = smem;                       // [i][g], 18*768 = 13824
    float* sh0  = sWih + IN0 * G3;            // layer-0 h, 2 bufs x [c][row16]
    float* sh1  = sh0 + 2 * H * NBP;          // layer-1 h, 2 bufs
    float* sx   = sh1 + 2 * H * NBP;          // x tile, 2 bufs x [i][row16]

    const int j = threadIdx.x;
    const int bbase = blk_start(blockIdx.x);
    const size_t xtile = (size_t)IN0 * NBP;

    for (int idx = j; idx < IN0 * G3; idx += NTHR) {
        int i = idx / G3, g = idx - i * G3;
        sWih[idx] = Wih0[g * IN0 + i];
    }
    // zero buffer 0 of both states (phase 0 reads buf 0)
    for (int idx = j; idx < H * NBP; idx += NTHR) {
        sh0[idx] = 0.f;
        sh1[idx] = 0.f;
    }
    // stage x(0) into sx[1] (prologue input) and x(1) into sx[0] (phase-0 input)
    {
        const float4* s0 = (const float4*)(g_xT + ((size_t)0 * NBLKK + blockIdx.x) * xtile);
        const float4* s1 = (const float4*)(g_xT + ((size_t)1 * NBLKK + blockIdx.x) * xtile);
        float4* d1 = (float4*)(sx + IN0 * NBP);
        float4* d0 = (float4*)sx;
        for (int idx = j; idx < IN0 * NBP / 4; idx += NTHR) {
            d1[idx] = s0[idx];
            d0[idx] = s1[idx];
        }
    }

    const float brz0 = bih0[j] + bhh0[j];
    const float bzz0 = bih0[H + j] + bhh0[H + j];
    const float bxn0 = bih0[2 * H + j];
    const float bhn0 = bhh0[2 * H + j];
    const float brz1 = bih1[j] + bhh1[j];
    const float bzz1 = bih1[H + j] + bhh1[H + j];
    const float bxn1 = bih1[2 * H + j];
    const float bhn1 = bhh1[2 * H + j];
    __syncthreads();

    // input projection K=18 from sxbuf into (ar, az, axn)
#define INPUT_PROJ(sxbuf, ar, az, axn)                                        \
    do {                                                                      \
        _Pragma("unroll")                                                     \
        for (int i = 0; i < IN0; i++) {                                       \
            float wr = sWih[i * G3 + j];                                      \
            float wz = sWih[i * G3 + H + j];                                  \
            float wn = sWih[i * G3 + 2 * H + j];                              \
            u64 wr2 = pk2(wr, wr), wz2 = pk2(wz, wz), wn2 = pk2(wn, wn);      \
            LOAD_ROW((sxbuf) + i * NBP, b0, b1, b2, b3v);                     \
            ROW_FMA(ar, wr2, b0, b1, b2, b3v);                                \
            ROW_FMA(az, wz2, b0, b1, b2, b3v);                                \
            ROW_FMA(axn, wn2, b0, b1, b2, b3v);                               \
        }                                                                     \
    } while (0)

    // ---------- prologue: h0(0) from x(0) (hidden state is zero) ----------
    {
        u64 a0r[7], a0z[7], a0xn[7], a0hn[7];
#pragma unroll
        for (int p = 0; p < 7; p++) {
            a0r[p] = pk2(brz0, brz0); a0z[p] = pk2(bzz0, bzz0);
            a0xn[p] = pk2(bxn0, bxn0); a0hn[p] = pk2(bhn0, bhn0);
        }
        INPUT_PROJ(sx + IN0 * NBP, a0r, a0z, a0xn);
        float hnew[NBR];
        float hzero[NBR];
#pragma unroll
        for (int b = 0; b < NBR; b++) hzero[b] = 0.f;
        epilogue(a0r, a0z, a0xn, a0hn, hzero, hnew);
        store_row(sh0 + j * NBP, hnew);   // h0(0) -> buf 0
    }
    __syncthreads();

    // ---------- main: 128 phases, one barrier each ----------
    for (int p = 0; p < T_STEPS; p++) {
        const int tc = p & 1, tn = tc ^ 1;
        const float* sh0c = sh0 + tc * (H * NBP);   // h0(p)
        float*       sh0n = sh0 + tn * (H * NBP);
        const float* sh1c = sh1 + tc * (H * NBP);   // h1(p-1)
        float*       sh1n = sh1 + tn * (H * NBP);
        const float* sxc  = sx + tc * (IN0 * NBP);  // x(p+1)

        u64 a1r[7], a1z[7], a1xn[7], a1hn[7];
        u64 a0r[7], a0z[7], a0xn[7], a0hn[7];
#pragma unroll
        for (int q = 0; q < 7; q++) {
            a1r[q] = pk2(brz1, brz1); a1z[q] = pk2(bzz1, bzz1);
            a1xn[q] = pk2(bxn1, bxn1); a1hn[q] = pk2(bhn1, bhn1);
            a0r[q] = pk2(brz0, brz0); a0z[q] = pk2(bzz0, bzz0);
            a0xn[q] = pk2(bxn0, bxn0); a0hn[q] = pk2(bhn0, bhn0);
        }

        INPUT_PROJ(sxc, a0r, a0z, a0xn);                      // L0(p+1) input part
        gemm_tri(sh0c, sh1c, a1r, a1z, a1xn, a1hn, a0r, a0z, a0hn, j);

        // stage x(p+2) into the other sx buffer
        if (p + 2 < T_STEPS) {
            const float4* src =
                (const float4*)(g_xT + ((size_t)(p + 2) * NBLKK + blockIdx.x) * xtile);
            float4* dst = (float4*)(sx + tn * (IN0 * NBP));
            for (int idx = j; idx < IN0 * NBP / 4; idx += NTHR) dst[idx] = src[idx];
        }

        // epilogue L1(p): h1(p) from h1(p-1)
        {
            float hnew[NBR];
            epilogue(a1r, a1z, a1xn, a1hn, sh1c + j * NBP, hnew);
            store_row(sh1n + j * NBP, hnew);
            if (p == T_STEPS - 1) {
#pragma unroll
                for (int b = 0; b < NBR; b++)
                    g_h2[(size_t)(bbase + b) * H + j] = hnew[b];
            }
        }
        // epilogue L0(p+1): h0(p+1) from h0(p)  (p=127: dead value, never read)
        {
            float hnew[NBR];
            epilogue(a0r, a0z, a0xn, a0hn, sh0c + j * NBP, hnew);
            store_row(sh0n + j * NBP, hnew);
        }
        __syncthreads();   // phase results visible
    }
#undef INPUT_PROJ
}

// ---------------- FC head ----------------
__global__ void k_fc(const float* __restrict__ fcw, const float* __restrict__ fcb,
                     float* __restrict__ out) {
    int warp = threadIdx.x >> 5, lane = threadIdx.x & 31;
    int row = blockIdx.x * 8 + warp;
    const float* h = &g_h2[(size_t)row * H];
    float a0 = 0.f, a1 = 0.f, a2 = 0.f, a3 = 0.f;
    for (int k = lane; k < H; k += 32) {
        float hv = h[k];
        a0 += hv * fcw[k];
        a1 += hv * fcw[H + k];
        a2 += hv * fcw[2 * H + k];
        a3 += hv * fcw[3 * H + k];
    }
#pragma unroll
    for (int off = 16; off; off >>= 1) {
        a0 += __shfl_xor_sync(0xffffffffu, a0, off);
        a1 += __shfl_xor_sync(0xffffffffu, a1, off);
        a2 += __shfl_xor_sync(0xffffffffu, a2, off);
        a3 += __shfl_xor_sync(0xffffffffu, a3, off);
    }
    if (lane == 0) {
        float l0 = a0 + fcb[0], l1 = a1 + fcb[1], l2 = a2 + fcb[2], l3 = a3 + fcb[3];
        out[row * 4 + 0] = 2.f / (1.f + expf(-l0)) - 1.f;
        out[row * 4 + 1] = 2.f / (1.f + expf(-l1)) - 1.f;
        out[row * 4 + 2] = 2.f / (1.f + expf(-l2)) - 1.f;
        out[row * 4 + 3] = 2.f / (1.f + expf(-l3)) - 1.f;
    }
}

extern "C" void kernel_launch(void* const* d_in, const int* in_sizes, int n_in,
                              void* d_out, int out_size) {
    const float* x    = (const float*)d_in[0];
    const float* Wih0 = (const float*)d_in[1];
    const float* Whh0 = (const float*)d_in[2];
    const float* bih0 = (const float*)d_in[3];
    const float* bhh0 = (const float*)d_in[4];
    const float* Wih1 = (const float*)d_in[5];
    const float* Whh1 = (const float*)d_in[6];
    const float* bih1 = (const float*)d_in[7];
    const float* bhh1 = (const float*)d_in[8];
    const float* fcw  = (const float*)d_in[9];
    const float* fcb  = (const float*)d_in[10];
    float* out = (float*)d_out;

    // floats: sWih 13824 + sh0 8192 + sh1 8192 + sx 576 = 30784 -> 123136 B
    const int gru_smem = (IN0 * G3 + 4 * H * NBP + 2 * IN0 * NBP) * (int)sizeof(float);
    static int smem_set = 0;
    if (!smem_set) {
        cudaFuncSetAttribute(k_gru, cudaFuncAttributeMaxDynamicSharedMemorySize, gru_smem);
        smem_set = 1;
    }

    {
        const size_t total = (size_t)T_STEPS * NBLKK * IN0 * NBR;
        k_xt<<<(int)((total + 255) / 256), 256>>>(x);
    }
    k_transpose<<<G3, 256>>>(Whh0, 0);
    k_transpose<<<G3, 256>>>(Whh1, 1);
    k_transpose<<<G3, 256>>>(Wih1, 2);
    k_gru<<<NBLKK, NTHR, gru_smem>>>(Wih0, bih0, bhh0, bih1, bhh1);
    k_fc<<<BATCH / 8, 256>>>(fcw, fcb, out);
}